// round 5
// baseline (speedup 1.0000x reference)
#include <cuda_runtime.h>

#define BINS    10
#define BLOCK   256
#define MAXGRID 1024

// Per-block partials: every block writes only its own slot -> no init kernel.
__device__ float        g_pcnt[MAXGRID][BINS];
__device__ float        g_psum[MAXGRID][BINS];
__device__ unsigned int g_arrive;   // zero at module load; last block resets it

// R1 hot path, verbatim: sigmoid, bin, stable BCE, two conflict-free scalar
// smem RMWs (layout [bin][tid]: lane==tid -> distinct banks for any bin mix).
__device__ __forceinline__ void process_elem(float x, float t, float lw,
                                             float* cnt_slot, float* sum_slot) {
    float u   = __expf(-x);               // FMUL + MUFU.EX2
    float w1  = 1.0f + u;
    float s   = __fdividef(1.0f, w1);     // sigmoid via MUFU.RCP
    float sp  = x + __logf(w1);           // softplus(x) = x + ln(1+e^{-x})
    float g10 = fabsf(s - t) * (float)BINS;
    int bin   = (int)g10;                 // g10 >= 0 -> trunc == floor
    bin = bin > (BINS - 1) ? (BINS - 1) : bin;
    float bce = fmaf(-x, t, sp);          // softplus(x) - x*t
    cnt_slot[bin * BLOCK] += lw;          // lw in {0,1} masks both sums
    sum_slot[bin * BLOCK] += bce * lw;
}

__global__ void __launch_bounds__(BLOCK)
ghmc_fused(const float4* __restrict__ pred4,
           const float4* __restrict__ targ4,
           const float4* __restrict__ lw4,
           int nquads, float* __restrict__ out) {
    __shared__ float s_cnt[BINS * BLOCK];   // 10 KB
    __shared__ float s_sum[BINS * BLOCK];   // 10 KB
    int tid = threadIdx.x;
    #pragma unroll
    for (int b = 0; b < BINS; b++) {
        s_cnt[b * BLOCK + tid] = 0.0f;
        s_sum[b * BLOCK + tid] = 0.0f;
    }
    __syncthreads();
    float* cnt_slot = &s_cnt[tid];
    float* sum_slot = &s_sum[tid];

    int stride = gridDim.x * BLOCK;
    for (int i = blockIdx.x * BLOCK + tid; i < nquads; i += stride) {
        float4 p = pred4[i];
        float4 t = targ4[i];
        float4 w = lw4[i];
        process_elem(p.x, t.x, w.x, cnt_slot, sum_slot);
        process_elem(p.y, t.y, w.y, cnt_slot, sum_slot);
        process_elem(p.z, t.z, w.z, cnt_slot, sum_slot);
        process_elem(p.w, t.w, w.w, cnt_slot, sum_slot);
    }
    __syncthreads();

    // Block tree-reduce the 256 private slots per bin (R1 form).
    for (int off = BLOCK / 2; off > 0; off >>= 1) {
        if (tid < off) {
            #pragma unroll
            for (int b = 0; b < BINS; b++) {
                s_cnt[b * BLOCK + tid] += s_cnt[b * BLOCK + tid + off];
                s_sum[b * BLOCK + tid] += s_sum[b * BLOCK + tid + off];
            }
        }
        __syncthreads();
    }
    if (tid < BINS) {
        g_pcnt[blockIdx.x][tid] = s_cnt[tid * BLOCK];
        g_psum[blockIdx.x][tid] = s_sum[tid * BLOCK];
    }

    // ---- last-block-done finalize (deterministic: counter self-resets) ----
    __shared__ unsigned int s_ticket;
    __threadfence();
    if (tid == 0) s_ticket = atomicAdd(&g_arrive, 1u);
    __syncthreads();
    if (s_ticket != gridDim.x - 1) return;

    __threadfence();  // acquire all blocks' partial writes
    int lane = tid & 31, wid = tid >> 5;
    float accC[BINS], accS[BINS];
    #pragma unroll
    for (int b = 0; b < BINS; b++) { accC[b] = 0.f; accS[b] = 0.f; }
    for (int k = tid; k < (int)gridDim.x; k += BLOCK) {
        #pragma unroll
        for (int b = 0; b < BINS; b++) {
            accC[b] += g_pcnt[k][b];
            accS[b] += g_psum[k][b];
        }
    }
    #pragma unroll
    for (int b = 0; b < BINS; b++) {
        #pragma unroll
        for (int off = 16; off > 0; off >>= 1) {
            accC[b] += __shfl_down_sync(0xffffffffu, accC[b], off);
            accS[b] += __shfl_down_sync(0xffffffffu, accS[b], off);
        }
    }
    __shared__ float2 s_red[BLOCK / 32][BINS];
    if (lane == 0)
        #pragma unroll
        for (int b = 0; b < BINS; b++) s_red[wid][b] = make_float2(accC[b], accS[b]);
    __syncthreads();
    if (tid == 0) {
        // loss = (1/n) * sum_b S[b]/counts[b]   (tot cancels exactly)
        double loss = 0.0;
        int n = 0;
        #pragma unroll
        for (int b = 0; b < BINS; b++) {
            double c = 0.0, s = 0.0;
            for (int w = 0; w < BLOCK / 32; w++) {
                c += (double)s_red[w][b].x;
                s += (double)s_red[w][b].y;
            }
            if (c > 0.0) { n++; loss += s / c; }
        }
        out[0] = (float)(n > 0 ? loss / (double)n : 0.0);
        g_arrive = 0u;   // pristine state for the next graph replay
    }
}

extern "C" void kernel_launch(void* const* d_in, const int* in_sizes, int n_in,
                              void* d_out, int out_size) {
    const float* pred = (const float*)d_in[0];
    const float* targ = (const float*)d_in[1];
    const float* lw   = (const float*)d_in[2];
    float* out = (float*)d_out;

    int n  = in_sizes[0];
    int nq = n / 4;   // N*C divisible by 4: no scalar tail

    int grid = 592;   // R1's measured-best launch shape: 4 blocks/SM
    int max_grid = (nq + BLOCK - 1) / BLOCK;
    if (max_grid < 1) max_grid = 1;
    if (grid > max_grid) grid = max_grid;

    ghmc_fused<<<grid, BLOCK>>>((const float4*)pred, (const float4*)targ,
                                (const float4*)lw, nq, out);
}

// round 6
// speedup vs baseline: 1.3772x; 1.3772x over previous
#include <cuda_runtime.h>

#define BINS    10
#define BLOCK   256
#define MAXGRID 1024

// Per-block partials: every block writes only its own slot -> no init kernel.
__device__ float2       g_part[MAXGRID][BINS];
__device__ unsigned int g_arrive;   // zero at module load; last block resets it

__device__ __forceinline__ void process_elem(float x, float t, float lw,
                                             float2* slot) {
    float u   = __expf(-x);               // FMUL + MUFU.EX2
    float w1  = 1.0f + u;
    float s   = __fdividef(1.0f, w1);     // sigmoid via MUFU.RCP
    float sp  = x + __logf(w1);           // softplus(x) = x + ln(1+e^{-x})
    float g10 = fabsf(s - t) * (float)BINS;
    int bin   = (int)g10;                 // g10 >= 0 -> trunc == floor
    bin = bin > (BINS - 1) ? (BINS - 1) : bin;
    float bce = fmaf(-x, t, sp);          // softplus(x) - x*t
    float2 a  = slot[bin * BLOCK];        // LDS.64
    a.x += lw;                            // lw in {0,1} masks both sums
    a.y += bce * lw;
    slot[bin * BLOCK] = a;                // STS.64
}

__global__ void __launch_bounds__(BLOCK)
ghmc_fused(const float4* __restrict__ pred4,
           const float4* __restrict__ targ4,
           const float4* __restrict__ lw4,
           int nquads, float* __restrict__ out) {
    // Two parity banks of [bin][tid] float2 slots (40 KB): conflict-free
    // (lane==tid at 8B granularity) and per-quad RMWs form two independent
    // 2-deep chains instead of one 4-deep chain.
    __shared__ float2 s_acc[2][BINS * BLOCK];
    int tid = threadIdx.x;
    #pragma unroll
    for (int b = 0; b < BINS; b++) {
        s_acc[0][b * BLOCK + tid] = make_float2(0.f, 0.f);
        s_acc[1][b * BLOCK + tid] = make_float2(0.f, 0.f);
    }
    __syncthreads();
    float2* slot0 = &s_acc[0][tid];
    float2* slot1 = &s_acc[1][tid];

    int stride = gridDim.x * BLOCK;
    int i = blockIdx.x * BLOCK + tid;

    // Software pipeline: iteration i+1's three LDG.128 issue before iteration
    // i's compute/smem chain, keeping MLP>=3 decoupled from the RMW chain.
    float4 p = make_float4(0.f, 0.f, 0.f, 0.f);
    float4 t = p, w = p;                  // lw=0 defaults: contribute nothing
    if (i < nquads) { p = pred4[i]; t = targ4[i]; w = lw4[i]; }

    #pragma unroll 1
    for (; i < nquads; ) {
        int j = i + stride;
        float4 pn, tn, wn;
        bool more = (j < nquads);
        if (more) { pn = pred4[j]; tn = targ4[j]; wn = lw4[j]; }
        process_elem(p.x, t.x, w.x, slot0);
        process_elem(p.y, t.y, w.y, slot1);
        process_elem(p.z, t.z, w.z, slot0);
        process_elem(p.w, t.w, w.w, slot1);
        if (!more) break;
        p = pn; t = tn; w = wn; i = j;
    }
    __syncthreads();

    // Block tree-reduction; fold parity bank 1 into bank 0 on the first pass.
    if (tid < 128) {
        #pragma unroll
        for (int b = 0; b < BINS; b++) {
            float2 a = s_acc[0][b * BLOCK + tid];
            float2 c = s_acc[0][b * BLOCK + tid + 128];
            float2 d = s_acc[1][b * BLOCK + tid];
            float2 e = s_acc[1][b * BLOCK + tid + 128];
            a.x += c.x + d.x + e.x;
            a.y += c.y + d.y + e.y;
            s_acc[0][b * BLOCK + tid] = a;
        }
    }
    __syncthreads();
    for (int off = 64; off > 0; off >>= 1) {
        if (tid < off) {
            #pragma unroll
            for (int b = 0; b < BINS; b++) {
                float2 a = s_acc[0][b * BLOCK + tid];
                float2 c = s_acc[0][b * BLOCK + tid + off];
                a.x += c.x; a.y += c.y;
                s_acc[0][b * BLOCK + tid] = a;
            }
        }
        __syncthreads();
    }
    if (tid < BINS)
        g_part[blockIdx.x][tid] = s_acc[0][tid * BLOCK];

    // ---- last-block-done finalize (deterministic: counter self-resets) ----
    __shared__ unsigned int s_ticket;
    __threadfence();
    if (tid == 0) s_ticket = atomicAdd(&g_arrive, 1u);
    __syncthreads();
    if (s_ticket != gridDim.x - 1) return;

    __threadfence();  // acquire all blocks' partial writes
    int lane = tid & 31, wid = tid >> 5;
    float2 acc[BINS];
    #pragma unroll
    for (int b = 0; b < BINS; b++) acc[b] = make_float2(0.f, 0.f);
    for (int k = tid; k < (int)gridDim.x; k += BLOCK) {
        #pragma unroll
        for (int b = 0; b < BINS; b++) {
            float2 v = g_part[k][b];
            acc[b].x += v.x; acc[b].y += v.y;
        }
    }
    #pragma unroll
    for (int b = 0; b < BINS; b++) {
        #pragma unroll
        for (int off = 16; off > 0; off >>= 1) {
            acc[b].x += __shfl_down_sync(0xffffffffu, acc[b].x, off);
            acc[b].y += __shfl_down_sync(0xffffffffu, acc[b].y, off);
        }
    }
    __shared__ float2 s_red[BLOCK / 32][BINS];
    if (lane == 0)
        #pragma unroll
        for (int b = 0; b < BINS; b++) s_red[wid][b] = acc[b];
    __syncthreads();
    if (tid == 0) {
        // loss = (1/n) * sum_b S[b]/counts[b]   (tot cancels exactly)
        double loss = 0.0;
        int n = 0;
        #pragma unroll
        for (int b = 0; b < BINS; b++) {
            double c = 0.0, s = 0.0;
            for (int w = 0; w < BLOCK / 32; w++) {
                c += (double)s_red[w][b].x;
                s += (double)s_red[w][b].y;
            }
            if (c > 0.0) { n++; loss += s / c; }
        }
        out[0] = (float)(n > 0 ? loss / (double)n : 0.0);
        g_arrive = 0u;   // pristine state for the next graph replay
    }
}

extern "C" void kernel_launch(void* const* d_in, const int* in_sizes, int n_in,
                              void* d_out, int out_size) {
    const float* pred = (const float*)d_in[0];
    const float* targ = (const float*)d_in[1];
    const float* lw   = (const float*)d_in[2];
    float* out = (float*)d_out;

    int n  = in_sizes[0];
    int nq = n / 4;   // N*C divisible by 4: no scalar tail

    int grid = 592;   // 4 blocks/SM * 148 SMs (40KB smem each), single wave
    int max_grid = (nq + BLOCK - 1) / BLOCK;
    if (max_grid < 1) max_grid = 1;
    if (grid > max_grid) grid = max_grid;

    ghmc_fused<<<grid, BLOCK>>>((const float4*)pred, (const float4*)targ,
                                (const float4*)lw, nq, out);
}